// round 13
// baseline (speedup 1.0000x reference)
#include <cuda_runtime.h>
#include <cstdint>
#include <math.h>

#define B_SZ   4096
#define F1     6272          // 32*14*14
#define HID    2048
#define NCLS   10
#define EPSV   1e-5f

// e4m3 encodings of +1.0 / -1.0
#define F8_P1  0x38
#define F8_M1  0xB8

// ---------------- static device scratch (no runtime allocation) ----------------
__device__ __align__(16) uint8_t g_act[(size_t)B_SZ * F1];  // 25.7 MB, e4m3 ±1
__device__ __align__(16) uint8_t g_w2b[(size_t)HID  * F1];  // 12.8 MB, e4m3 ±1
__device__ float g_part[(size_t)16 * B_SZ * NCLS];          // 2.6 MB partial logits
__device__ int   g_cnt[32];                                 // per-mt arrival counters (reset each run)

// =============================== helpers ===============================

__device__ __forceinline__ uint32_t smem_u32(const void* p) {
    return (uint32_t)__cvta_generic_to_shared(p);
}

__device__ __forceinline__ void cp16(uint32_t dst, const void* src) {
    asm volatile("cp.async.cg.shared.global [%0], [%1], 16;"
                 :: "r"(dst), "l"(src) : "memory");
}

// fp8 e4m3 MMA, f32 accumulate. ±1 operands => every partial sum is an exact
// integer (|.| <= 6272 < 2^24), so f32 accumulation is exact in any order.
__device__ __forceinline__ void mma_f8(float* d, const uint32_t* a, const uint32_t* b) {
    asm volatile(
        "mma.sync.aligned.m16n8k32.row.col.f32.e4m3.e4m3.f32 "
        "{%0,%1,%2,%3}, {%4,%5,%6,%7}, {%8,%9}, {%0,%1,%2,%3};"
        : "+f"(d[0]), "+f"(d[1]), "+f"(d[2]), "+f"(d[3])
        : "r"(a[0]), "r"(a[1]), "r"(a[2]), "r"(a[3]), "r"(b[0]), "r"(b[1]));
}

__device__ __forceinline__ void ldsm4(uint32_t* r, uint32_t addr) {
    asm volatile("ldmatrix.sync.aligned.m8n8.x4.shared.b16 {%0,%1,%2,%3}, [%4];"
                 : "=r"(r[0]), "=r"(r[1]), "=r"(r[2]), "=r"(r[3]) : "r"(addr));
}

// =============================== kernel 1: fused prep + W2 sign-pack + conv ===============================
// One launch, block-id dispatch:
//   blocks [0, W2B_BLKS)     : W2 f32 -> e4m3 ±1 sign pack (memory-bound)
//   blocks [W2B_BLKS, +B_SZ) : conv layer for one image     (compute-bound)

#define W2B_N4    ((size_t)HID * F1 / 4)          // 3,211,264 float4s
#define W2B_BLKS  7168                            // 448 f4 per block

__global__ void __launch_bounds__(448) k_pre(
    const float* __restrict__ x,  const float* __restrict__ W1,
    const float* __restrict__ b1, const float* __restrict__ g1,
    const float* __restrict__ be1,const float* __restrict__ m1,
    const float* __restrict__ v1, const float* __restrict__ W2)
{
    const int tid = threadIdx.x;

    if (blockIdx.x < W2B_BLKS) {                  // ---- W2 sign-pack (e4m3) ----
        size_t i = (size_t)blockIdx.x * 448 + tid;
        if (i < W2B_N4) {
            float4 v = ((const float4*)W2)[i];
            uint32_t p = (uint32_t)(v.x >= 0.f ? F8_P1 : F8_M1)
                       | ((uint32_t)(v.y >= 0.f ? F8_P1 : F8_M1) << 8)
                       | ((uint32_t)(v.z >= 0.f ? F8_P1 : F8_M1) << 16)
                       | ((uint32_t)(v.w >= 0.f ? F8_P1 : F8_M1) << 24);
            ((uint32_t*)g_w2b)[i] = p;
        }
        return;
    }

    // ---- conv layer: sign(x) conv sign(W1) (pad 1) + b1 -> maxpool -> BN -> hardtanh -> sign ----
    // internal math stays int8 dp4a (exact); OUTPUT bytes are e4m3 ±1 for the fp8 GEMM.
    __shared__ int8_t   s8[30 * 36];
    __shared__ uint32_t wpA[96], wpB[96];
    __shared__ int      ithr[32];
    __shared__ uint8_t  ob[F1];

    const int img = blockIdx.x - W2B_BLKS;

    for (int i = tid; i < 30 * 36 / 4; i += 448) ((uint32_t*)s8)[i] = 0;
    if (tid < 96) {     // per-channel weight-row byte packs (A: bytes0-2, B: bytes1-3)
        int ch = tid / 3, j = tid % 3;
        const float* wr = W1 + ch * 9 + j * 3;
        uint32_t b0 = (uint8_t)(int8_t)(wr[0] >= 0.f ? 1 : -1);
        uint32_t bb = (uint8_t)(int8_t)(wr[1] >= 0.f ? 1 : -1);
        uint32_t b2 = (uint8_t)(int8_t)(wr[2] >= 0.f ? 1 : -1);
        wpA[tid] = b0 | (bb << 8) | (b2 << 16);
        wpB[tid] = (b0 << 8) | (bb << 16) | (b2 << 24);
    }
    if (tid < 32) {
        // thr = m1 - be1*sqrt(v1+eps)/g1 - b1 (g1>0); integer mx => ceil(thr) exact
        double sq = sqrt((double)v1[tid] + (double)EPSV);
        double thr = (double)m1[tid] - (double)be1[tid] * sq / (double)g1[tid] - (double)b1[tid];
        ithr[tid] = (int)ceil(thr);
    }
    __syncthreads();

    const float* xi = x + (size_t)img * 784;
    for (int i = tid; i < 784; i += 448) {
        int h = i / 28, w = i % 28;
        s8[(h + 1) * 36 + (w + 1)] = (xi[i] >= 0.f) ? (int8_t)1 : (int8_t)-1;
    }
    __syncthreads();

    const int ch = tid / 14, ph = tid % 14;        // 32*14 = 448 threads exactly
    const uint32_t wA0 = wpA[ch*3+0], wA1 = wpA[ch*3+1], wA2 = wpA[ch*3+2];
    const uint32_t wB0 = wpB[ch*3+0], wB1 = wpB[ch*3+1], wB2 = wpB[ch*3+2];
    const int thc = ithr[ch];
    const uint32_t* r0p = (const uint32_t*)(s8 + (2*ph + 0) * 36);
    const uint32_t* r1p = (const uint32_t*)(s8 + (2*ph + 1) * 36);
    const uint32_t* r2p = (const uint32_t*)(s8 + (2*ph + 2) * 36);
    const uint32_t* r3p = (const uint32_t*)(s8 + (2*ph + 3) * 36);

    #pragma unroll 2
    for (int pw = 0; pw < 14; ++pw) {
        int cb = 2 * pw, w0 = cb >> 2;
        uint32_t win0, win1, win2, win3;
        if (cb & 2) {
            win0 = __byte_perm(r0p[w0], r0p[w0+1], 0x5432);
            win1 = __byte_perm(r1p[w0], r1p[w0+1], 0x5432);
            win2 = __byte_perm(r2p[w0], r2p[w0+1], 0x5432);
            win3 = __byte_perm(r3p[w0], r3p[w0+1], 0x5432);
        } else {
            win0 = r0p[w0]; win1 = r1p[w0]; win2 = r2p[w0]; win3 = r3p[w0];
        }
        int c00 = __dp4a((int)win2, (int)wA2, __dp4a((int)win1, (int)wA1, __dp4a((int)win0, (int)wA0, 0)));
        int c01 = __dp4a((int)win2, (int)wB2, __dp4a((int)win1, (int)wB1, __dp4a((int)win0, (int)wB0, 0)));
        int c10 = __dp4a((int)win3, (int)wA2, __dp4a((int)win2, (int)wA1, __dp4a((int)win1, (int)wA0, 0)));
        int c11 = __dp4a((int)win3, (int)wB2, __dp4a((int)win2, (int)wB1, __dp4a((int)win1, (int)wB0, 0)));
        int mx = max(max(c00, c01), max(c10, c11));
        ob[ch * 196 + ph * 14 + pw] = (mx >= thc) ? (uint8_t)F8_P1 : (uint8_t)F8_M1;
    }
    __syncthreads();

    uint32_t* dst = (uint32_t*)(g_act + (size_t)img * F1);
    const uint32_t* src = (const uint32_t*)ob;
    for (int i = tid; i < F1 / 4; i += 448) dst[i] = src[i];
}

// =============================== kernel 2: fp8 mma.sync GEMM + fused epilogue + fused final ===============================
// CTA tile M=128 x N=128, 256 threads: 8 warps in 2(M)x4(N) grid, warp tile 64x32, 2 CTAs/SM.
// Instruction-flavor experiment: s8 IMMA pinned at ~45% pipe active across 5 configs
// (~940 MAC/cyc/SM = 46% of legacy peak) -> try e4m3 QMMA, which may map natively onto
// Blackwell's fp-centric tensor datapath. f32 accumulate is exact for ±1 operands.

#define KC      128
#define NSTG    3
#define RSTR    144                   // padded smem row stride (bank-conflict-free)
#define STG_A   (128 * RSTR)          // 18432
#define STG_B   (128 * RSTR)          // 18432
#define STG_SZ  (STG_A + STG_B)       // 36864
#define GEMM_DSMEM (NSTG * STG_SZ)    // 110592

__device__ __forceinline__ void load_stage(const uint8_t* A0, const uint8_t* B0,
                                           uint32_t stg, int k0, int tid) {
    #pragma unroll
    for (int j = 0; j < 8; ++j) {                 // 2048 x 16B chunks / 256 threads
        int chn = tid + j * 256;
        if (chn < 1024) {                         // A: 128 rows x 8 granules
            int row = chn >> 3, c16 = chn & 7;
            cp16(stg + (uint32_t)row * RSTR + (uint32_t)c16 * 16,
                 A0 + (size_t)row * F1 + k0 + c16 * 16);
        } else {                                  // B: 128 rows x 8 granules
            int bc = chn - 1024;
            int row = bc >> 3, c16 = bc & 7;
            cp16(stg + STG_A + (uint32_t)row * RSTR + (uint32_t)c16 * 16,
                 B0 + (size_t)row * F1 + k0 + c16 * 16);
        }
    }
}

__global__ void __launch_bounds__(256, 2) k_gemm(
    const float* __restrict__ b2, const float* __restrict__ g2,
    const float* __restrict__ be2, const float* __restrict__ m2,
    const float* __restrict__ v2, const float* __restrict__ W3,
    const float* __restrict__ b3, float* __restrict__ out)
{
    extern __shared__ char dsm[];
    const uint32_t sb = smem_u32(dsm);
    const int tid = threadIdx.x, lane = tid & 31, wid = tid >> 5;
    const int wm = wid >> 2, wn = wid & 3;        // 2(M) x 4(N) warp grid, 64x32 tiles
    const int nt = blockIdx.x, mt = blockIdx.y;
    const int m0 = mt * 128, n0 = nt * 128;

    const uint8_t* A0 = g_act + (size_t)m0 * F1;
    const uint8_t* B0 = g_w2b + (size_t)n0 * F1;

    // prologue: stages 0,1
    load_stage(A0, B0, sb + 0 * STG_SZ, 0,  tid);
    asm volatile("cp.async.commit_group;" ::: "memory");
    load_stage(A0, B0, sb + 1 * STG_SZ, KC, tid);
    asm volatile("cp.async.commit_group;" ::: "memory");

    float acc[4][4][4];                           // [mb 16-rows][nb 8-cols][frag], exact ints
    #pragma unroll
    for (int i = 0; i < 4; ++i)
        #pragma unroll
        for (int j = 0; j < 4; ++j)
            #pragma unroll
            for (int r = 0; r < 4; ++r) acc[i][j][r] = 0.f;

    const uint32_t aoffT = (uint32_t)(wm * 64 + (lane & 7) + ((lane >> 3) & 1) * 8) * RSTR
                         + ((lane >> 4) & 1) * 16;
    const uint32_t boffT = STG_A
                         + (uint32_t)(wn * 32 + (lane & 7) + ((lane >> 4) & 1) * 8) * RSTR
                         + ((lane >> 3) & 1) * 16;

    for (int k = 0; k < 49; ++k) {
        const int buf = k - (k / 3) * 3;
        asm volatile("cp.async.wait_group 1;" ::: "memory");
        __syncthreads();
        const int kn = k + 2;
        if (kn < 49) {
            const int bn = kn - (kn / 3) * 3;
            load_stage(A0, B0, sb + bn * STG_SZ, kn * KC, tid);
        }
        asm volatile("cp.async.commit_group;" ::: "memory");

        const uint32_t sA = sb + buf * STG_SZ;
        uint32_t a[2][4][4], b[2][2][4];
        #pragma unroll
        for (int mb = 0; mb < 4; ++mb)
            ldsm4(a[0][mb], sA + aoffT + mb * (16 * RSTR));
        #pragma unroll
        for (int nbp = 0; nbp < 2; ++nbp)
            ldsm4(b[0][nbp], sA + boffT + nbp * (16 * RSTR));

        #pragma unroll
        for (int ks = 0; ks < 4; ++ks) {
            const int cur = ks & 1, nxt = cur ^ 1;
            if (ks < 3) {
                #pragma unroll
                for (int mb = 0; mb < 4; ++mb)
                    ldsm4(a[nxt][mb], sA + aoffT + mb * (16 * RSTR) + (ks + 1) * 32);
                #pragma unroll
                for (int nbp = 0; nbp < 2; ++nbp)
                    ldsm4(b[nxt][nbp], sA + boffT + nbp * (16 * RSTR) + (ks + 1) * 32);
            }
            #pragma unroll
            for (int nbp = 0; nbp < 2; ++nbp)
                #pragma unroll
                for (int mb = 0; mb < 4; ++mb) {
                    mma_f8(acc[mb][2 * nbp],     a[cur][mb], b[cur][nbp]);
                    mma_f8(acc[mb][2 * nbp + 1], a[cur][mb], b[cur][nbp] + 2);
                }
        }
    }
    __syncthreads();                                  // compute done; reuse smem

    // ---- epilogue: b2 + BN2 + hardtanh, then partial logits vs W3 ----
    float* sp = (float*)dsm;                          // [4 warp_n][128 rows][10] = 20 KB
    float* tb = (float*)(dsm + 20480);                // tables: 5*128 + 128*10 floats
    if (tid < 128) {
        int n = n0 + tid;
        tb[tid]       = b2[n];
        tb[128 + tid] = g2[n];
        tb[256 + tid] = m2[n];
        tb[384 + tid] = 1.0f / sqrtf(v2[n] + EPSV);
        tb[512 + tid] = be2[n];
    }
    for (int i = tid; i < 1280; i += 256) {
        int col = i / 10, c = i - col * 10;
        tb[640 + i] = W3[(size_t)c * HID + n0 + col];
    }
    __syncthreads();

    #pragma unroll
    for (int mb = 0; mb < 4; ++mb) {
        #pragma unroll
        for (int half = 0; half < 2; ++half) {
            int row = wm * 64 + mb * 16 + (lane >> 2) + 8 * half;
            float l10[NCLS];
            #pragma unroll
            for (int c = 0; c < NCLS; ++c) l10[c] = 0.f;
            #pragma unroll
            for (int nb = 0; nb < 4; ++nb) {
                #pragma unroll
                for (int e = 0; e < 2; ++e) {
                    int col = wn * 32 + nb * 8 + 2 * (lane & 3) + e;
                    float z = acc[mb][nb][half * 2 + e] + tb[col];          // + b2 (exact int)
                    float t = tb[128 + col] * (z - tb[256 + col]);          // g2*(z-m2)
                    t *= tb[384 + col]; t += tb[512 + col];                 // *rs + be2
                    t = fminf(1.f, fmaxf(-1.f, t));                         // hardtanh
                    const float* w3c = tb + 640 + col * 10;
                    #pragma unroll
                    for (int c = 0; c < NCLS; ++c) l10[c] = fmaf(t, w3c[c], l10[c]);
                }
            }
            #pragma unroll
            for (int c = 0; c < NCLS; ++c) {
                l10[c] += __shfl_xor_sync(0xffffffffu, l10[c], 1);
                l10[c] += __shfl_xor_sync(0xffffffffu, l10[c], 2);
            }
            if ((lane & 3) == 0) {
                float* d = sp + ((size_t)wn * 128 + row) * NCLS;
                #pragma unroll
                for (int c = 0; c < NCLS; ++c) d[c] = l10[c];
            }
        }
    }
    __syncthreads();

    for (int i = tid; i < 128 * NCLS; i += 256) {
        int row = i / NCLS, c = i - row * NCLS;
        float s = sp[(0 * 128 + row) * NCLS + c] + sp[(1 * 128 + row) * NCLS + c]
                + sp[(2 * 128 + row) * NCLS + c] + sp[(3 * 128 + row) * NCLS + c];
        g_part[((size_t)nt * B_SZ + m0 + row) * NCLS + c] = s;
    }

    // ---- fused final: last CTA of this mt row-block reduces + b3 + log_softmax ----
    __threadfence();                                  // publish g_part slice
    __shared__ int s_last;
    if (tid == 0) s_last = (atomicAdd(&g_cnt[mt], 1) == 15);
    __syncthreads();
    if (!s_last) return;
    __threadfence();                                  // acquire: see all 16 slices

    if (tid < 128) {
        int row = m0 + tid;
        float l[NCLS];
        #pragma unroll
        for (int c = 0; c < NCLS; ++c) l[c] = b3[c];
        #pragma unroll
        for (int p = 0; p < 16; ++p) {                // fixed order: deterministic
            const float* s = g_part + ((size_t)p * B_SZ + row) * NCLS;
            #pragma unroll
            for (int c = 0; c < NCLS; ++c) l[c] += s[c];
        }
        float mx = l[0];
        #pragma unroll
        for (int c = 1; c < NCLS; ++c) mx = fmaxf(mx, l[c]);
        float sum = 0.f;
        #pragma unroll
        for (int c = 0; c < NCLS; ++c) sum += expf(l[c] - mx);
        float lse = mx + logf(sum);
        #pragma unroll
        for (int c = 0; c < NCLS; ++c) out[row * NCLS + c] = l[c] - lse;
    }
    __syncthreads();
    if (tid == 0) g_cnt[mt] = 0;                      // reset for next graph replay
}

// =============================== launcher ===============================

extern "C" void kernel_launch(void* const* d_in, const int* in_sizes, int n_in,
                              void* d_out, int out_size) {
    const float* x   = (const float*)d_in[0];
    const float* W1  = (const float*)d_in[1];
    const float* b1  = (const float*)d_in[2];
    const float* g1  = (const float*)d_in[3];
    const float* be1 = (const float*)d_in[4];
    const float* m1  = (const float*)d_in[5];
    const float* v1  = (const float*)d_in[6];
    const float* W2  = (const float*)d_in[7];
    const float* b2  = (const float*)d_in[8];
    const float* g2  = (const float*)d_in[9];
    const float* be2 = (const float*)d_in[10];
    const float* m2  = (const float*)d_in[11];
    const float* v2  = (const float*)d_in[12];
    const float* W3  = (const float*)d_in[13];
    const float* b3  = (const float*)d_in[14];

    cudaFuncSetAttribute(k_gemm, cudaFuncAttributeMaxDynamicSharedMemorySize, GEMM_DSMEM);

    k_pre<<<W2B_BLKS + B_SZ, 448>>>(x, W1, b1, g1, be1, m1, v1, W2);
    k_gemm<<<dim3(16, 32), 256, GEMM_DSMEM>>>(b2, g2, be2, m2, v2, W3, b3, (float*)d_out);
}

// round 14
// speedup vs baseline: 2.2306x; 2.2306x over previous
#include <cuda_runtime.h>
#include <cstdint>
#include <math.h>

#define B_SZ   4096
#define F1     6272          // 32*14*14
#define HID    2048
#define NCLS   10
#define EPSV   1e-5f

// ---------------- static device scratch (no runtime allocation) ----------------
__device__ __align__(16) int8_t g_act[(size_t)B_SZ * F1];   // 25.7 MB, ±1
__device__ __align__(16) int8_t g_w2b[(size_t)HID  * F1];   // 12.8 MB, ±1
__device__ float g_part[(size_t)16 * B_SZ * NCLS];          // 2.6 MB partial logits

// =============================== helpers ===============================

__device__ __forceinline__ uint32_t smem_u32(const void* p) {
    return (uint32_t)__cvta_generic_to_shared(p);
}

__device__ __forceinline__ void cp16(uint32_t dst, const void* src) {
    asm volatile("cp.async.cg.shared.global [%0], [%1], 16;"
                 :: "r"(dst), "l"(src) : "memory");
}

__device__ __forceinline__ void mma_s8(int* d, const uint32_t* a, const uint32_t* b) {
    asm volatile(
        "mma.sync.aligned.m16n8k32.row.col.s32.s8.s8.s32 "
        "{%0,%1,%2,%3}, {%4,%5,%6,%7}, {%8,%9}, {%0,%1,%2,%3};"
        : "+r"(d[0]), "+r"(d[1]), "+r"(d[2]), "+r"(d[3])
        : "r"(a[0]), "r"(a[1]), "r"(a[2]), "r"(a[3]), "r"(b[0]), "r"(b[1]));
}

__device__ __forceinline__ void ldsm4(uint32_t* r, uint32_t addr) {
    asm volatile("ldmatrix.sync.aligned.m8n8.x4.shared.b16 {%0,%1,%2,%3}, [%4];"
                 : "=r"(r[0]), "=r"(r[1]), "=r"(r[2]), "=r"(r[3]) : "r"(addr));
}

// =============================== kernel 1: fused W2 sign-pack + conv ===============================
// One launch, block-id dispatch:
//   blocks [0, W2B_BLKS)     : W2 f32 -> int8 ±1 sign pack (memory-bound)
//   blocks [W2B_BLKS, +B_SZ) : conv layer for one image     (compute-bound)
// Running both block types concurrently overlaps w2bin's DRAM traffic with conv compute.

#define W2B_N4    ((size_t)HID * F1 / 4)          // 3,211,264 float4s
#define W2B_BLKS  7168                            // 448 f4 per block

__global__ void __launch_bounds__(448) k_pre(
    const float* __restrict__ x,  const float* __restrict__ W1,
    const float* __restrict__ b1, const float* __restrict__ g1,
    const float* __restrict__ be1,const float* __restrict__ m1,
    const float* __restrict__ v1, const float* __restrict__ W2)
{
    const int tid = threadIdx.x;

    if (blockIdx.x < W2B_BLKS) {                  // ---- W2 sign-pack ----
        size_t i = (size_t)blockIdx.x * 448 + tid;
        if (i < W2B_N4) {
            float4 v = ((const float4*)W2)[i];
            uint32_t p = (uint32_t)(uint8_t)(int8_t)(v.x >= 0.f ? 1 : -1)
                       | ((uint32_t)(uint8_t)(int8_t)(v.y >= 0.f ? 1 : -1) << 8)
                       | ((uint32_t)(uint8_t)(int8_t)(v.z >= 0.f ? 1 : -1) << 16)
                       | ((uint32_t)(uint8_t)(int8_t)(v.w >= 0.f ? 1 : -1) << 24);
            ((uint32_t*)g_w2b)[i] = p;
        }
        return;
    }

    // ---- conv layer: sign(x) conv sign(W1) (pad 1) + b1 -> maxpool -> BN -> hardtanh -> sign ----
    // conv output is an exact integer; BN+sign collapses to int-vs-int threshold (exact).
    __shared__ int8_t   s8[30 * 36];
    __shared__ uint32_t wpA[96], wpB[96];
    __shared__ int      ithr[32];
    __shared__ int8_t   ob[F1];

    const int img = blockIdx.x - W2B_BLKS;

    for (int i = tid; i < 30 * 36 / 4; i += 448) ((uint32_t*)s8)[i] = 0;
    if (tid < 96) {     // per-channel weight-row byte packs (A: bytes0-2, B: bytes1-3)
        int ch = tid / 3, j = tid % 3;
        const float* wr = W1 + ch * 9 + j * 3;
        uint32_t b0 = (uint8_t)(int8_t)(wr[0] >= 0.f ? 1 : -1);
        uint32_t bb = (uint8_t)(int8_t)(wr[1] >= 0.f ? 1 : -1);
        uint32_t b2 = (uint8_t)(int8_t)(wr[2] >= 0.f ? 1 : -1);
        wpA[tid] = b0 | (bb << 8) | (b2 << 16);
        wpB[tid] = (b0 << 8) | (bb << 16) | (b2 << 24);
    }
    if (tid < 32) {
        // thr = m1 - be1*sqrt(v1+eps)/g1 - b1 (g1>0); integer mx => ceil(thr) exact
        double sq = sqrt((double)v1[tid] + (double)EPSV);
        double thr = (double)m1[tid] - (double)be1[tid] * sq / (double)g1[tid] - (double)b1[tid];
        ithr[tid] = (int)ceil(thr);
    }
    __syncthreads();

    const float* xi = x + (size_t)img * 784;
    for (int i = tid; i < 784; i += 448) {
        int h = i / 28, w = i % 28;
        s8[(h + 1) * 36 + (w + 1)] = (xi[i] >= 0.f) ? (int8_t)1 : (int8_t)-1;
    }
    __syncthreads();

    const int ch = tid / 14, ph = tid % 14;        // 32*14 = 448 threads exactly
    const uint32_t wA0 = wpA[ch*3+0], wA1 = wpA[ch*3+1], wA2 = wpA[ch*3+2];
    const uint32_t wB0 = wpB[ch*3+0], wB1 = wpB[ch*3+1], wB2 = wpB[ch*3+2];
    const int thc = ithr[ch];
    const uint32_t* r0p = (const uint32_t*)(s8 + (2*ph + 0) * 36);
    const uint32_t* r1p = (const uint32_t*)(s8 + (2*ph + 1) * 36);
    const uint32_t* r2p = (const uint32_t*)(s8 + (2*ph + 2) * 36);
    const uint32_t* r3p = (const uint32_t*)(s8 + (2*ph + 3) * 36);

    #pragma unroll 2
    for (int pw = 0; pw < 14; ++pw) {
        int cb = 2 * pw, w0 = cb >> 2;
        uint32_t win0, win1, win2, win3;
        if (cb & 2) {
            win0 = __byte_perm(r0p[w0], r0p[w0+1], 0x5432);
            win1 = __byte_perm(r1p[w0], r1p[w0+1], 0x5432);
            win2 = __byte_perm(r2p[w0], r2p[w0+1], 0x5432);
            win3 = __byte_perm(r3p[w0], r3p[w0+1], 0x5432);
        } else {
            win0 = r0p[w0]; win1 = r1p[w0]; win2 = r2p[w0]; win3 = r3p[w0];
        }
        int c00 = __dp4a((int)win2, (int)wA2, __dp4a((int)win1, (int)wA1, __dp4a((int)win0, (int)wA0, 0)));
        int c01 = __dp4a((int)win2, (int)wB2, __dp4a((int)win1, (int)wB1, __dp4a((int)win0, (int)wB0, 0)));
        int c10 = __dp4a((int)win3, (int)wA2, __dp4a((int)win2, (int)wA1, __dp4a((int)win1, (int)wA0, 0)));
        int c11 = __dp4a((int)win3, (int)wB2, __dp4a((int)win2, (int)wB1, __dp4a((int)win1, (int)wB0, 0)));
        int mx = max(max(c00, c01), max(c10, c11));
        ob[ch * 196 + ph * 14 + pw] = (mx >= thc) ? (int8_t)1 : (int8_t)-1;
    }
    __syncthreads();

    uint32_t* dst = (uint32_t*)(g_act + (size_t)img * F1);
    const uint32_t* src = (const uint32_t*)ob;
    for (int i = tid; i < F1 / 4; i += 448) dst[i] = src[i];
}

// =============================== kernel 2: int8 mma.sync GEMM + fused epilogue ===============================
// Byte-identical to the measured-best round-9 mainloop (204.6 us): CTA tile 128x128,
// 256 threads, 8 warps 2(M)x4(N) 64x32 tiles, 2 CTAs/SM, 3-stage cp.async, KC=128,
// register-double-buffered ldsm fragments. s8 IMMA at ~940 MAC/cyc/SM is this chip's
// legacy-path ceiling (fp8 flavor: 2.5x slower, emulated) — mainloop is at its floor.

#define KC      128
#define NSTG    3
#define RSTR    144                   // padded smem row stride (bank-conflict-free)
#define STG_A   (128 * RSTR)          // 18432
#define STG_B   (128 * RSTR)          // 18432
#define STG_SZ  (STG_A + STG_B)       // 36864
#define GEMM_DSMEM (NSTG * STG_SZ)    // 110592

__device__ __forceinline__ void load_stage(const int8_t* A0, const int8_t* B0,
                                           uint32_t stg, int k0, int tid) {
    #pragma unroll
    for (int j = 0; j < 8; ++j) {                 // 2048 x 16B chunks / 256 threads
        int chn = tid + j * 256;
        if (chn < 1024) {                         // A: 128 rows x 8 granules
            int row = chn >> 3, c16 = chn & 7;
            cp16(stg + (uint32_t)row * RSTR + (uint32_t)c16 * 16,
                 A0 + (size_t)row * F1 + k0 + c16 * 16);
        } else {                                  // B: 128 rows x 8 granules
            int bc = chn - 1024;
            int row = bc >> 3, c16 = bc & 7;
            cp16(stg + STG_A + (uint32_t)row * RSTR + (uint32_t)c16 * 16,
                 B0 + (size_t)row * F1 + k0 + c16 * 16);
        }
    }
}

__global__ void __launch_bounds__(256, 2) k_gemm(
    const float* __restrict__ b2, const float* __restrict__ g2,
    const float* __restrict__ be2, const float* __restrict__ m2,
    const float* __restrict__ v2, const float* __restrict__ W3)
{
    extern __shared__ char dsm[];
    const uint32_t sb = smem_u32(dsm);
    const int tid = threadIdx.x, lane = tid & 31, wid = tid >> 5;
    const int wm = wid >> 2, wn = wid & 3;        // 2(M) x 4(N) warp grid, 64x32 tiles
    const int nt = blockIdx.x, mt = blockIdx.y;
    const int m0 = mt * 128, n0 = nt * 128;

    const int8_t* A0 = g_act + (size_t)m0 * F1;
    const int8_t* B0 = g_w2b + (size_t)n0 * F1;

    // prologue: stages 0,1
    load_stage(A0, B0, sb + 0 * STG_SZ, 0,  tid);
    asm volatile("cp.async.commit_group;" ::: "memory");
    load_stage(A0, B0, sb + 1 * STG_SZ, KC, tid);
    asm volatile("cp.async.commit_group;" ::: "memory");

    int acc[4][4][4];                             // [mb 16-rows][nb 8-cols][frag]
    #pragma unroll
    for (int i = 0; i < 4; ++i)
        #pragma unroll
        for (int j = 0; j < 4; ++j)
            #pragma unroll
            for (int r = 0; r < 4; ++r) acc[i][j][r] = 0;

    const uint32_t aoffT = (uint32_t)(wm * 64 + (lane & 7) + ((lane >> 3) & 1) * 8) * RSTR
                         + ((lane >> 4) & 1) * 16;
    const uint32_t boffT = STG_A
                         + (uint32_t)(wn * 32 + (lane & 7) + ((lane >> 4) & 1) * 8) * RSTR
                         + ((lane >> 3) & 1) * 16;

    for (int k = 0; k < 49; ++k) {
        const int buf = k - (k / 3) * 3;
        asm volatile("cp.async.wait_group 1;" ::: "memory");
        __syncthreads();
        const int kn = k + 2;
        if (kn < 49) {
            const int bn = kn - (kn / 3) * 3;
            load_stage(A0, B0, sb + bn * STG_SZ, kn * KC, tid);
        }
        asm volatile("cp.async.commit_group;" ::: "memory");

        const uint32_t sA = sb + buf * STG_SZ;
        uint32_t a[2][4][4], b[2][2][4];
        #pragma unroll
        for (int mb = 0; mb < 4; ++mb)
            ldsm4(a[0][mb], sA + aoffT + mb * (16 * RSTR));
        #pragma unroll
        for (int nbp = 0; nbp < 2; ++nbp)
            ldsm4(b[0][nbp], sA + boffT + nbp * (16 * RSTR));

        #pragma unroll
        for (int ks = 0; ks < 4; ++ks) {
            const int cur = ks & 1, nxt = cur ^ 1;
            if (ks < 3) {
                #pragma unroll
                for (int mb = 0; mb < 4; ++mb)
                    ldsm4(a[nxt][mb], sA + aoffT + mb * (16 * RSTR) + (ks + 1) * 32);
                #pragma unroll
                for (int nbp = 0; nbp < 2; ++nbp)
                    ldsm4(b[nxt][nbp], sA + boffT + nbp * (16 * RSTR) + (ks + 1) * 32);
            }
            #pragma unroll
            for (int nbp = 0; nbp < 2; ++nbp)
                #pragma unroll
                for (int mb = 0; mb < 4; ++mb) {
                    mma_s8(acc[mb][2 * nbp],     a[cur][mb], b[cur][nbp]);
                    mma_s8(acc[mb][2 * nbp + 1], a[cur][mb], b[cur][nbp] + 2);
                }
        }
    }
    __syncthreads();                                  // compute done; reuse smem

    // ---- epilogue: b2 + BN2 + hardtanh, then partial logits vs W3 ----
    float* sp = (float*)dsm;                          // [4 warp_n][128 rows][10] = 20 KB
    float* tb = (float*)(dsm + 20480);                // tables: 5*128 + 128*10 floats
    if (tid < 128) {
        int n = n0 + tid;
        tb[tid]       = b2[n];
        tb[128 + tid] = g2[n];
        tb[256 + tid] = m2[n];
        tb[384 + tid] = 1.0f / sqrtf(v2[n] + EPSV);
        tb[512 + tid] = be2[n];
    }
    for (int i = tid; i < 1280; i += 256) {
        int col = i / 10, c = i - col * 10;
        tb[640 + i] = W3[(size_t)c * HID + n0 + col];
    }
    __syncthreads();

    #pragma unroll
    for (int mb = 0; mb < 4; ++mb) {
        #pragma unroll
        for (int half = 0; half < 2; ++half) {
            int row = wm * 64 + mb * 16 + (lane >> 2) + 8 * half;
            float l10[NCLS];
            #pragma unroll
            for (int c = 0; c < NCLS; ++c) l10[c] = 0.f;
            #pragma unroll
            for (int nb = 0; nb < 4; ++nb) {
                #pragma unroll
                for (int e = 0; e < 2; ++e) {
                    int col = wn * 32 + nb * 8 + 2 * (lane & 3) + e;
                    float z = (float)acc[mb][nb][half * 2 + e] + tb[col];   // + b2 (exact int)
                    float t = tb[128 + col] * (z - tb[256 + col]);          // g2*(z-m2)
                    t *= tb[384 + col]; t += tb[512 + col];                 // *rs + be2
                    t = fminf(1.f, fmaxf(-1.f, t));                         // hardtanh
                    const float* w3c = tb + 640 + col * 10;
                    #pragma unroll
                    for (int c = 0; c < NCLS; ++c) l10[c] = fmaf(t, w3c[c], l10[c]);
                }
            }
            #pragma unroll
            for (int c = 0; c < NCLS; ++c) {
                l10[c] += __shfl_xor_sync(0xffffffffu, l10[c], 1);
                l10[c] += __shfl_xor_sync(0xffffffffu, l10[c], 2);
            }
            if ((lane & 3) == 0) {
                float* d = sp + ((size_t)wn * 128 + row) * NCLS;
                #pragma unroll
                for (int c = 0; c < NCLS; ++c) d[c] = l10[c];
            }
        }
    }
    __syncthreads();

    for (int i = tid; i < 128 * NCLS; i += 256) {
        int row = i / NCLS, c = i - row * NCLS;
        float s = sp[(0 * 128 + row) * NCLS + c] + sp[(1 * 128 + row) * NCLS + c]
                + sp[(2 * 128 + row) * NCLS + c] + sp[(3 * 128 + row) * NCLS + c];
        g_part[((size_t)nt * B_SZ + m0 + row) * NCLS + c] = s;
    }
}

// =============================== kernel 3: reduce + b3 + log_softmax ===============================

__global__ void __launch_bounds__(256) k_final(const float* __restrict__ b3,
                                               float* __restrict__ out) {
    int row = blockIdx.x * 256 + threadIdx.x;     // 4096 rows
    float l[NCLS];
    #pragma unroll
    for (int c = 0; c < NCLS; ++c) l[c] = b3[c];
    #pragma unroll
    for (int p = 0; p < 16; ++p) {
        const float* s = g_part + ((size_t)p * B_SZ + row) * NCLS;
        #pragma unroll
        for (int c = 0; c < NCLS; ++c) l[c] += s[c];
    }
    float m = l[0];
    #pragma unroll
    for (int c = 1; c < NCLS; ++c) m = fmaxf(m, l[c]);
    float sum = 0.f;
    #pragma unroll
    for (int c = 0; c < NCLS; ++c) sum += expf(l[c] - m);
    float lse = m + logf(sum);
    #pragma unroll
    for (int c = 0; c < NCLS; ++c) out[row * NCLS + c] = l[c] - lse;
}

// =============================== launcher ===============================

extern "C" void kernel_launch(void* const* d_in, const int* in_sizes, int n_in,
                              void* d_out, int out_size) {
    const float* x   = (const float*)d_in[0];
    const float* W1  = (const float*)d_in[1];
    const float* b1  = (const float*)d_in[2];
    const float* g1  = (const float*)d_in[3];
    const float* be1 = (const float*)d_in[4];
    const float* m1  = (const float*)d_in[5];
    const float* v1  = (const float*)d_in[6];
    const float* W2  = (const float*)d_in[7];
    const float* b2  = (const float*)d_in[8];
    const float* g2  = (const float*)d_in[9];
    const float* be2 = (const float*)d_in[10];
    const float* m2  = (const float*)d_in[11];
    const float* v2  = (const float*)d_in[12];
    const float* W3  = (const float*)d_in[13];
    const float* b3  = (const float*)d_in[14];

    cudaFuncSetAttribute(k_gemm, cudaFuncAttributeMaxDynamicSharedMemorySize, GEMM_DSMEM);

    k_pre<<<W2B_BLKS + B_SZ, 448>>>(x, W1, b1, g1, be1, m1, v1, W2);
    k_gemm<<<dim3(16, 32), 256, GEMM_DSMEM>>>(b2, g2, be2, m2, v2, W3);
    k_final<<<16, 256>>>(b3, (float*)d_out);
}

// round 16
// speedup vs baseline: 2.2674x; 1.0165x over previous
#include <cuda_runtime.h>
#include <cstdint>
#include <math.h>

#define B_SZ   4096
#define F1     6272          // 32*14*14
#define HID    2048
#define NCLS   10
#define EPSV   1e-5f

// ---------------- static device scratch (no runtime allocation) ----------------
__device__ __align__(16) int8_t g_act[(size_t)B_SZ * F1];   // 25.7 MB, ±1
__device__ __align__(16) int8_t g_w2b[(size_t)HID  * F1];   // 12.8 MB, ±1
__device__ float g_part[(size_t)16 * B_SZ * NCLS];          // 2.6 MB partial logits

// =============================== helpers ===============================

__device__ __forceinline__ uint32_t smem_u32(const void* p) {
    return (uint32_t)__cvta_generic_to_shared(p);
}

__device__ __forceinline__ void cp16(uint32_t dst, const void* src) {
    asm volatile("cp.async.cg.shared.global [%0], [%1], 16;"
                 :: "r"(dst), "l"(src) : "memory");
}

__device__ __forceinline__ void mma_s8(int* d, const uint32_t* a, const uint32_t* b) {
    asm volatile(
        "mma.sync.aligned.m16n8k32.row.col.s32.s8.s8.s32 "
        "{%0,%1,%2,%3}, {%4,%5,%6,%7}, {%8,%9}, {%0,%1,%2,%3};"
        : "+r"(d[0]), "+r"(d[1]), "+r"(d[2]), "+r"(d[3])
        : "r"(a[0]), "r"(a[1]), "r"(a[2]), "r"(a[3]), "r"(b[0]), "r"(b[1]));
}

__device__ __forceinline__ void ldsm4(uint32_t* r, uint32_t addr) {
    asm volatile("ldmatrix.sync.aligned.m8n8.x4.shared.b16 {%0,%1,%2,%3}, [%4];"
                 : "=r"(r[0]), "=r"(r[1]), "=r"(r[2]), "=r"(r[3]) : "r"(addr));
}

// =============================== kernel 1: fused W2 sign-pack + conv ===============================
// One launch, block-id dispatch:
//   blocks [0, W2B_BLKS)     : W2 f32 -> int8 ±1 sign pack (memory-bound)
//   blocks [W2B_BLKS, +B_SZ) : conv layer for one image     (compute-bound)
// Conv inner loop uses a REGISTER-CACHED sliding window (round-14 ncu: L1 57.5%,
// issue 61.5% -> LDS traffic was the k_pre bottleneck): 32 LDS/thread vs ~84.

#define W2B_N4    ((size_t)HID * F1 / 4)          // 3,211,264 float4s
#define W2B_BLKS  7168                            // 448 f4 per block

__global__ void __launch_bounds__(448) k_pre(
    const float* __restrict__ x,  const float* __restrict__ W1,
    const float* __restrict__ b1, const float* __restrict__ g1,
    const float* __restrict__ be1,const float* __restrict__ m1,
    const float* __restrict__ v1, const float* __restrict__ W2)
{
    const int tid = threadIdx.x;

    if (blockIdx.x < W2B_BLKS) {                  // ---- W2 sign-pack ----
        size_t i = (size_t)blockIdx.x * 448 + tid;
        if (i < W2B_N4) {
            float4 v = ((const float4*)W2)[i];
            uint32_t p = (uint32_t)(uint8_t)(int8_t)(v.x >= 0.f ? 1 : -1)
                       | ((uint32_t)(uint8_t)(int8_t)(v.y >= 0.f ? 1 : -1) << 8)
                       | ((uint32_t)(uint8_t)(int8_t)(v.z >= 0.f ? 1 : -1) << 16)
                       | ((uint32_t)(uint8_t)(int8_t)(v.w >= 0.f ? 1 : -1) << 24);
            ((uint32_t*)g_w2b)[i] = p;
        }
        return;
    }

    // ---- conv layer: sign(x) conv sign(W1) (pad 1) + b1 -> maxpool -> BN -> hardtanh -> sign ----
    // conv output is an exact integer; BN+sign collapses to int-vs-int threshold (exact).
    __shared__ int8_t   s8[30 * 36];
    __shared__ uint32_t wpA[96], wpB[96];
    __shared__ int      ithr[32];
    __shared__ __align__(16) int8_t ob[F1];

    const int img = blockIdx.x - W2B_BLKS;

    for (int i = tid; i < 30 * 36 / 4; i += 448) ((uint32_t*)s8)[i] = 0;
    if (tid < 96) {     // per-channel weight-row byte packs (A: bytes0-2, B: bytes1-3)
        int ch = tid / 3, j = tid % 3;
        const float* wr = W1 + ch * 9 + j * 3;
        uint32_t b0 = (uint8_t)(int8_t)(wr[0] >= 0.f ? 1 : -1);
        uint32_t bb = (uint8_t)(int8_t)(wr[1] >= 0.f ? 1 : -1);
        uint32_t b2 = (uint8_t)(int8_t)(wr[2] >= 0.f ? 1 : -1);
        wpA[tid] = b0 | (bb << 8) | (b2 << 16);
        wpB[tid] = (b0 << 8) | (bb << 16) | (b2 << 24);
    }
    if (tid < 32) {
        // thr = m1 - be1*sqrt(v1+eps)/g1 - b1 (g1>0); integer mx => ceil(thr) exact
        double sq = sqrt((double)v1[tid] + (double)EPSV);
        double thr = (double)m1[tid] - (double)be1[tid] * sq / (double)g1[tid] - (double)b1[tid];
        ithr[tid] = (int)ceil(thr);
    }
    __syncthreads();

    const float* xi = x + (size_t)img * 784;
    for (int i = tid; i < 784; i += 448) {
        int h = i / 28, w = i % 28;
        s8[(h + 1) * 36 + (w + 1)] = (xi[i] >= 0.f) ? (int8_t)1 : (int8_t)-1;
    }
    __syncthreads();

    const int ch = tid / 14, ph = tid % 14;        // 32*14 = 448 threads exactly
    const uint32_t wA0 = wpA[ch*3+0], wA1 = wpA[ch*3+1], wA2 = wpA[ch*3+2];
    const uint32_t wB0 = wpB[ch*3+0], wB1 = wpB[ch*3+1], wB2 = wpB[ch*3+2];
    const int thc = ithr[ch];
    const uint32_t* r0p = (const uint32_t*)(s8 + (2*ph + 0) * 36);
    const uint32_t* r1p = (const uint32_t*)(s8 + (2*ph + 1) * 36);
    const uint32_t* r2p = (const uint32_t*)(s8 + (2*ph + 2) * 36);
    const uint32_t* r3p = (const uint32_t*)(s8 + (2*ph + 3) * 36);

    // register-cached sliding window: cur = word t, nxt = word t+1 per row.
    // pw = 2t   (even): window = cur                  (bytes 4t..4t+3)
    // pw = 2t+1 (odd) : window = perm(cur,nxt,0x5432) (bytes 4t+2..4t+5)
    int8_t* obp = ob + ch * 196 + ph * 14;
    uint32_t c0 = r0p[0], c1 = r1p[0], c2 = r2p[0], c3 = r3p[0];
    #pragma unroll
    for (int t = 0; t < 7; ++t) {
        const uint32_t n0 = r0p[t+1], n1 = r1p[t+1], n2 = r2p[t+1], n3 = r3p[t+1];
        // even pw = 2t
        {
            int e00 = __dp4a((int)c2, (int)wA2, __dp4a((int)c1, (int)wA1, __dp4a((int)c0, (int)wA0, 0)));
            int e01 = __dp4a((int)c2, (int)wB2, __dp4a((int)c1, (int)wB1, __dp4a((int)c0, (int)wB0, 0)));
            int e10 = __dp4a((int)c3, (int)wA2, __dp4a((int)c2, (int)wA1, __dp4a((int)c1, (int)wA0, 0)));
            int e11 = __dp4a((int)c3, (int)wB2, __dp4a((int)c2, (int)wB1, __dp4a((int)c1, (int)wB0, 0)));
            int mx = max(max(e00, e01), max(e10, e11));
            obp[2*t] = (mx >= thc) ? (int8_t)1 : (int8_t)-1;
        }
        // odd pw = 2t+1
        {
            uint32_t w0v = __byte_perm(c0, n0, 0x5432);
            uint32_t w1v = __byte_perm(c1, n1, 0x5432);
            uint32_t w2v = __byte_perm(c2, n2, 0x5432);
            uint32_t w3v = __byte_perm(c3, n3, 0x5432);
            int o00 = __dp4a((int)w2v, (int)wA2, __dp4a((int)w1v, (int)wA1, __dp4a((int)w0v, (int)wA0, 0)));
            int o01 = __dp4a((int)w2v, (int)wB2, __dp4a((int)w1v, (int)wB1, __dp4a((int)w0v, (int)wB0, 0)));
            int o10 = __dp4a((int)w3v, (int)wA2, __dp4a((int)w2v, (int)wA1, __dp4a((int)w1v, (int)wA0, 0)));
            int o11 = __dp4a((int)w3v, (int)wB2, __dp4a((int)w2v, (int)wB1, __dp4a((int)w1v, (int)wB0, 0)));
            int mx = max(max(o00, o01), max(o10, o11));
            obp[2*t + 1] = (mx >= thc) ? (int8_t)1 : (int8_t)-1;
        }
        c0 = n0; c1 = n1; c2 = n2; c3 = n3;
    }
    __syncthreads();

    uint4* dst = (uint4*)(g_act + (size_t)img * F1);  // F1 = 392 * 16 -> uint4 clean
    const uint4* src = (const uint4*)ob;
    if (tid < 392) dst[tid] = src[tid];
}

// =============================== kernel 2: int8 mma.sync GEMM + fused epilogue ===============================
// Byte-identical to the measured-best round-9 mainloop (204.6 us): CTA tile 128x128,
// 256 threads, 8 warps 2(M)x4(N) 64x32 tiles, 2 CTAs/SM, 3-stage cp.async, KC=128,
// register-double-buffered ldsm fragments. s8 IMMA at ~940 MAC/cyc/SM is this chip's
// legacy-path ceiling (fp8 flavor: 2.5x slower, emulated) — mainloop is at its floor.

#define KC      128
#define NSTG    3
#define RSTR    144                   // padded smem row stride (bank-conflict-free)
#define STG_A   (128 * RSTR)          // 18432
#define STG_B   (128 * RSTR)          // 18432
#define STG_SZ  (STG_A + STG_B)       // 36864
#define GEMM_DSMEM (NSTG * STG_SZ)    // 110592

__device__ __forceinline__ void load_stage(const int8_t* A0, const int8_t* B0,
                                           uint32_t stg, int k0, int tid) {
    #pragma unroll
    for (int j = 0; j < 8; ++j) {                 // 2048 x 16B chunks / 256 threads
        int chn = tid + j * 256;
        if (chn < 1024) {                         // A: 128 rows x 8 granules
            int row = chn >> 3, c16 = chn & 7;
            cp16(stg + (uint32_t)row * RSTR + (uint32_t)c16 * 16,
                 A0 + (size_t)row * F1 + k0 + c16 * 16);
        } else {                                  // B: 128 rows x 8 granules
            int bc = chn - 1024;
            int row = bc >> 3, c16 = bc & 7;
            cp16(stg + STG_A + (uint32_t)row * RSTR + (uint32_t)c16 * 16,
                 B0 + (size_t)row * F1 + k0 + c16 * 16);
        }
    }
}

__global__ void __launch_bounds__(256, 2) k_gemm(
    const float* __restrict__ b2, const float* __restrict__ g2,
    const float* __restrict__ be2, const float* __restrict__ m2,
    const float* __restrict__ v2, const float* __restrict__ W3)
{
    extern __shared__ char dsm[];
    const uint32_t sb = smem_u32(dsm);
    const int tid = threadIdx.x, lane = tid & 31, wid = tid >> 5;
    const int wm = wid >> 2, wn = wid & 3;        // 2(M) x 4(N) warp grid, 64x32 tiles
    const int nt = blockIdx.x, mt = blockIdx.y;
    const int m0 = mt * 128, n0 = nt * 128;

    const int8_t* A0 = g_act + (size_t)m0 * F1;
    const int8_t* B0 = g_w2b + (size_t)n0 * F1;

    // prologue: stages 0,1
    load_stage(A0, B0, sb + 0 * STG_SZ, 0,  tid);
    asm volatile("cp.async.commit_group;" ::: "memory");
    load_stage(A0, B0, sb + 1 * STG_SZ, KC, tid);
    asm volatile("cp.async.commit_group;" ::: "memory");

    int acc[4][4][4];                             // [mb 16-rows][nb 8-cols][frag]
    #pragma unroll
    for (int i = 0; i < 4; ++i)
        #pragma unroll
        for (int j = 0; j < 4; ++j)
            #pragma unroll
            for (int r = 0; r < 4; ++r) acc[i][j][r] = 0;

    const uint32_t aoffT = (uint32_t)(wm * 64 + (lane & 7) + ((lane >> 3) & 1) * 8) * RSTR
                         + ((lane >> 4) & 1) * 16;
    const uint32_t boffT = STG_A
                         + (uint32_t)(wn * 32 + (lane & 7) + ((lane >> 4) & 1) * 8) * RSTR
                         + ((lane >> 3) & 1) * 16;

    for (int k = 0; k < 49; ++k) {
        const int buf = k - (k / 3) * 3;
        asm volatile("cp.async.wait_group 1;" ::: "memory");
        __syncthreads();
        const int kn = k + 2;
        if (kn < 49) {
            const int bn = kn - (kn / 3) * 3;
            load_stage(A0, B0, sb + bn * STG_SZ, kn * KC, tid);
        }
        asm volatile("cp.async.commit_group;" ::: "memory");

        const uint32_t sA = sb + buf * STG_SZ;
        uint32_t a[2][4][4], b[2][2][4];
        #pragma unroll
        for (int mb = 0; mb < 4; ++mb)
            ldsm4(a[0][mb], sA + aoffT + mb * (16 * RSTR));
        #pragma unroll
        for (int nbp = 0; nbp < 2; ++nbp)
            ldsm4(b[0][nbp], sA + boffT + nbp * (16 * RSTR));

        #pragma unroll
        for (int ks = 0; ks < 4; ++ks) {
            const int cur = ks & 1, nxt = cur ^ 1;
            if (ks < 3) {
                #pragma unroll
                for (int mb = 0; mb < 4; ++mb)
                    ldsm4(a[nxt][mb], sA + aoffT + mb * (16 * RSTR) + (ks + 1) * 32);
                #pragma unroll
                for (int nbp = 0; nbp < 2; ++nbp)
                    ldsm4(b[nxt][nbp], sA + boffT + nbp * (16 * RSTR) + (ks + 1) * 32);
            }
            #pragma unroll
            for (int nbp = 0; nbp < 2; ++nbp)
                #pragma unroll
                for (int mb = 0; mb < 4; ++mb) {
                    mma_s8(acc[mb][2 * nbp],     a[cur][mb], b[cur][nbp]);
                    mma_s8(acc[mb][2 * nbp + 1], a[cur][mb], b[cur][nbp] + 2);
                }
        }
    }
    __syncthreads();                                  // compute done; reuse smem

    // ---- epilogue: b2 + BN2 + hardtanh, then partial logits vs W3 ----
    float* sp = (float*)dsm;                          // [4 warp_n][128 rows][10] = 20 KB
    float* tb = (float*)(dsm + 20480);                // tables: 5*128 + 128*10 floats
    if (tid < 128) {
        int n = n0 + tid;
        tb[tid]       = b2[n];
        tb[128 + tid] = g2[n];
        tb[256 + tid] = m2[n];
        tb[384 + tid] = 1.0f / sqrtf(v2[n] + EPSV);
        tb[512 + tid] = be2[n];
    }
    for (int i = tid; i < 1280; i += 256) {
        int col = i / 10, c = i - col * 10;
        tb[640 + i] = W3[(size_t)c * HID + n0 + col];
    }
    __syncthreads();

    #pragma unroll
    for (int mb = 0; mb < 4; ++mb) {
        #pragma unroll
        for (int half = 0; half < 2; ++half) {
            int row = wm * 64 + mb * 16 + (lane >> 2) + 8 * half;
            float l10[NCLS];
            #pragma unroll
            for (int c = 0; c < NCLS; ++c) l10[c] = 0.f;
            #pragma unroll
            for (int nb = 0; nb < 4; ++nb) {
                #pragma unroll
                for (int e = 0; e < 2; ++e) {
                    int col = wn * 32 + nb * 8 + 2 * (lane & 3) + e;
                    float z = (float)acc[mb][nb][half * 2 + e] + tb[col];   // + b2 (exact int)
                    float t = tb[128 + col] * (z - tb[256 + col]);          // g2*(z-m2)
                    t *= tb[384 + col]; t += tb[512 + col];                 // *rs + be2
                    t = fminf(1.f, fmaxf(-1.f, t));                         // hardtanh
                    const float* w3c = tb + 640 + col * 10;
                    #pragma unroll
                    for (int c = 0; c < NCLS; ++c) l10[c] = fmaf(t, w3c[c], l10[c]);
                }
            }
            #pragma unroll
            for (int c = 0; c < NCLS; ++c) {
                l10[c] += __shfl_xor_sync(0xffffffffu, l10[c], 1);
                l10[c] += __shfl_xor_sync(0xffffffffu, l10[c], 2);
            }
            if ((lane & 3) == 0) {
                float* d = sp + ((size_t)wn * 128 + row) * NCLS;
                #pragma unroll
                for (int c = 0; c < NCLS; ++c) d[c] = l10[c];
            }
        }
    }
    __syncthreads();

    for (int i = tid; i < 128 * NCLS; i += 256) {
        int row = i / NCLS, c = i - row * NCLS;
        float s = sp[(0 * 128 + row) * NCLS + c] + sp[(1 * 128 + row) * NCLS + c]
                + sp[(2 * 128 + row) * NCLS + c] + sp[(3 * 128 + row) * NCLS + c];
        g_part[((size_t)nt * B_SZ + m0 + row) * NCLS + c] = s;
    }
}

// =============================== kernel 3: reduce + b3 + log_softmax ===============================

__global__ void __launch_bounds__(256) k_final(const float* __restrict__ b3,
                                               float* __restrict__ out) {
    int row = blockIdx.x * 256 + threadIdx.x;     // 4096 rows
    float l[NCLS];
    #pragma unroll
    for (int c = 0; c < NCLS; ++c) l[c] = b3[c];
    #pragma unroll
    for (int p = 0; p < 16; ++p) {
        const float* s = g_part + ((size_t)p * B_SZ + row) * NCLS;
        #pragma unroll
        for (int c = 0; c < NCLS; ++c) l[c] += s[c];
    }
    float m = l[0];
    #pragma unroll
    for (int c = 1; c < NCLS; ++c) m = fmaxf(m, l[c]);
    float sum = 0.f;
    #pragma unroll
    for (int c = 0; c < NCLS; ++c) sum += expf(l[c] - m);
    float lse = m + logf(sum);
    #pragma unroll
    for (int c = 0; c < NCLS; ++c) out[row * NCLS + c] = l[c] - lse;
}

// =============================== launcher ===============================

extern "C" void kernel_launch(void* const* d_in, const int* in_sizes, int n_in,
                              void* d_out, int out_size) {
    const float* x   = (const float*)d_in[0];
    const float* W1  = (const float*)d_in[1];
    const float* b1  = (const float*)d_in[2];
    const float* g1  = (const float*)d_in[3];
    const float* be1 = (const float*)d_in[4];
    const float* m1  = (const float*)d_in[5];
    const float* v1  = (const float*)d_in[6];
    const float* W2  = (const float*)d_in[7];
    const float* b2  = (const float*)d_in[8];
    const float* g2  = (const float*)d_in[9];
    const float* be2 = (const float*)d_in[10];
    const float* m2  = (const float*)d_in[11];
    const float* v2  = (const float*)d_in[12];
    const float* W3  = (const float*)d_in[13];
    const float* b3  = (const float*)d_in[14];

    cudaFuncSetAttribute(k_gemm, cudaFuncAttributeMaxDynamicSharedMemorySize, GEMM_DSMEM);

    k_pre<<<W2B_BLKS + B_SZ, 448>>>(x, W1, b1, g1, be1, m1, v1, W2);
    k_gemm<<<dim3(16, 32), 256, GEMM_DSMEM>>>(b2, g2, be2, m2, v2, W3);
    k_final<<<16, 256>>>(b3, (float*)d_out);
}

// round 17
// speedup vs baseline: 2.3046x; 1.0164x over previous
#include <cuda_runtime.h>
#include <cstdint>
#include <math.h>

#define B_SZ   4096
#define F1     6272          // 32*14*14
#define HID    2048
#define NCLS   10
#define EPSV   1e-5f

// ---------------- static device scratch (no runtime allocation) ----------------
__device__ __align__(16) int8_t g_act[(size_t)B_SZ * F1];   // 25.7 MB, ±1
__device__ __align__(16) int8_t g_w2b[(size_t)HID  * F1];   // 12.8 MB, ±1
__device__ float g_part[(size_t)16 * B_SZ * NCLS];          // 2.6 MB partial logits

// =============================== helpers ===============================

__device__ __forceinline__ uint32_t smem_u32(const void* p) {
    return (uint32_t)__cvta_generic_to_shared(p);
}

__device__ __forceinline__ void cp16(uint32_t dst, const void* src) {
    asm volatile("cp.async.cg.shared.global [%0], [%1], 16;"
                 :: "r"(dst), "l"(src) : "memory");
}

__device__ __forceinline__ void mma_s8(int* d, const uint32_t* a, const uint32_t* b) {
    asm volatile(
        "mma.sync.aligned.m16n8k32.row.col.s32.s8.s8.s32 "
        "{%0,%1,%2,%3}, {%4,%5,%6,%7}, {%8,%9}, {%0,%1,%2,%3};"
        : "+r"(d[0]), "+r"(d[1]), "+r"(d[2]), "+r"(d[3])
        : "r"(a[0]), "r"(a[1]), "r"(a[2]), "r"(a[3]), "r"(b[0]), "r"(b[1]));
}

__device__ __forceinline__ void ldsm4(uint32_t* r, uint32_t addr) {
    asm volatile("ldmatrix.sync.aligned.m8n8.x4.shared.b16 {%0,%1,%2,%3}, [%4];"
                 : "=r"(r[0]), "=r"(r[1]), "=r"(r[2]), "=r"(r[3]) : "r"(addr));
}

__device__ __forceinline__ uint32_t sgn4(float a, float b, float c, float d) {
    return (uint32_t)(uint8_t)(int8_t)(a >= 0.f ? 1 : -1)
         | ((uint32_t)(uint8_t)(int8_t)(b >= 0.f ? 1 : -1) << 8)
         | ((uint32_t)(uint8_t)(int8_t)(c >= 0.f ? 1 : -1) << 16)
         | ((uint32_t)(uint8_t)(int8_t)(d >= 0.f ? 1 : -1) << 24);
}

// =============================== kernel 1: fused conv + W2 sign-pack ===============================
// One launch, block-id dispatch — CONV FIRST so the compute pole starts immediately,
// w2bin (memory) blocks stream into residual slots:
//   blocks [0, B_SZ)             : conv layer for one image (compute-bound)
//   blocks [B_SZ, B_SZ+W2B_BLKS) : W2 f32 -> int8 ±1 sign pack, 4 float4/thread (MLP 4)

#define W2B_BLKS  1792                            // 1792 blocks x 1792 f4 = 3,211,264 exactly

__global__ void __launch_bounds__(448) k_pre(
    const float* __restrict__ x,  const float* __restrict__ W1,
    const float* __restrict__ b1, const float* __restrict__ g1,
    const float* __restrict__ be1,const float* __restrict__ m1,
    const float* __restrict__ v1, const float* __restrict__ W2)
{
    const int tid = threadIdx.x;

    if (blockIdx.x >= B_SZ) {                     // ---- W2 sign-pack, MLP=4 ----
        size_t base = (size_t)(blockIdx.x - B_SZ) * 1792 + tid;
        const float4* w4 = (const float4*)W2;
        float4 v0 = w4[base];
        float4 v1 = w4[base + 448];
        float4 v2 = w4[base + 896];
        float4 v3 = w4[base + 1344];
        uint32_t* o = (uint32_t*)g_w2b;
        o[base]        = sgn4(v0.x, v0.y, v0.z, v0.w);
        o[base + 448]  = sgn4(v1.x, v1.y, v1.z, v1.w);
        o[base + 896]  = sgn4(v2.x, v2.y, v2.z, v2.w);
        o[base + 1344] = sgn4(v3.x, v3.y, v3.z, v3.w);
        return;
    }

    // ---- conv layer: sign(x) conv sign(W1) (pad 1) + b1 -> maxpool -> BN -> hardtanh -> sign ----
    // conv output is an exact integer; BN+sign collapses to int-vs-int threshold (exact).
    __shared__ int8_t   s8[30 * 36];
    __shared__ uint32_t wpA[96], wpB[96];
    __shared__ int      ithr[32];
    __shared__ __align__(16) int8_t ob[F1];

    const int img = blockIdx.x;

    for (int i = tid; i < 30 * 36 / 4; i += 448) ((uint32_t*)s8)[i] = 0;
    if (tid < 96) {     // per-channel weight-row byte packs (A: bytes0-2, B: bytes1-3)
        int ch = tid / 3, j = tid % 3;
        const float* wr = W1 + ch * 9 + j * 3;
        uint32_t b0 = (uint8_t)(int8_t)(wr[0] >= 0.f ? 1 : -1);
        uint32_t bb = (uint8_t)(int8_t)(wr[1] >= 0.f ? 1 : -1);
        uint32_t b2 = (uint8_t)(int8_t)(wr[2] >= 0.f ? 1 : -1);
        wpA[tid] = b0 | (bb << 8) | (b2 << 16);
        wpB[tid] = (b0 << 8) | (bb << 16) | (b2 << 24);
    }
    if (tid < 32) {
        // thr = m1 - be1*sqrt(v1+eps)/g1 - b1 (g1>0); integer mx => ceil(thr) exact
        double sq = sqrt((double)v1[tid] + (double)EPSV);
        double thr = (double)m1[tid] - (double)be1[tid] * sq / (double)g1[tid] - (double)b1[tid];
        ithr[tid] = (int)ceil(thr);
    }
    __syncthreads();

    const float* xi = x + (size_t)img * 784;
    for (int i = tid; i < 784; i += 448) {
        int h = i / 28, w = i % 28;
        s8[(h + 1) * 36 + (w + 1)] = (xi[i] >= 0.f) ? (int8_t)1 : (int8_t)-1;
    }
    __syncthreads();

    const int ch = tid / 14, ph = tid % 14;        // 32*14 = 448 threads exactly
    const uint32_t wA0 = wpA[ch*3+0], wA1 = wpA[ch*3+1], wA2 = wpA[ch*3+2];
    const uint32_t wB0 = wpB[ch*3+0], wB1 = wpB[ch*3+1], wB2 = wpB[ch*3+2];
    const int thc = ithr[ch];
    const uint32_t* r0p = (const uint32_t*)(s8 + (2*ph + 0) * 36);
    const uint32_t* r1p = (const uint32_t*)(s8 + (2*ph + 1) * 36);
    const uint32_t* r2p = (const uint32_t*)(s8 + (2*ph + 2) * 36);
    const uint32_t* r3p = (const uint32_t*)(s8 + (2*ph + 3) * 36);

    // register-cached sliding window: cur = word t, nxt = word t+1 per row.
    // pw = 2t   (even): window = cur                  (bytes 4t..4t+3)
    // pw = 2t+1 (odd) : window = perm(cur,nxt,0x5432) (bytes 4t+2..4t+5)
    int8_t* obp = ob + ch * 196 + ph * 14;
    uint32_t c0 = r0p[0], c1 = r1p[0], c2 = r2p[0], c3 = r3p[0];
    #pragma unroll
    for (int t = 0; t < 7; ++t) {
        const uint32_t n0 = r0p[t+1], n1 = r1p[t+1], n2 = r2p[t+1], n3 = r3p[t+1];
        // even pw = 2t
        {
            int e00 = __dp4a((int)c2, (int)wA2, __dp4a((int)c1, (int)wA1, __dp4a((int)c0, (int)wA0, 0)));
            int e01 = __dp4a((int)c2, (int)wB2, __dp4a((int)c1, (int)wB1, __dp4a((int)c0, (int)wB0, 0)));
            int e10 = __dp4a((int)c3, (int)wA2, __dp4a((int)c2, (int)wA1, __dp4a((int)c1, (int)wA0, 0)));
            int e11 = __dp4a((int)c3, (int)wB2, __dp4a((int)c2, (int)wB1, __dp4a((int)c1, (int)wB0, 0)));
            int mx = max(max(e00, e01), max(e10, e11));
            obp[2*t] = (mx >= thc) ? (int8_t)1 : (int8_t)-1;
        }
        // odd pw = 2t+1
        {
            uint32_t w0v = __byte_perm(c0, n0, 0x5432);
            uint32_t w1v = __byte_perm(c1, n1, 0x5432);
            uint32_t w2v = __byte_perm(c2, n2, 0x5432);
            uint32_t w3v = __byte_perm(c3, n3, 0x5432);
            int o00 = __dp4a((int)w2v, (int)wA2, __dp4a((int)w1v, (int)wA1, __dp4a((int)w0v, (int)wA0, 0)));
            int o01 = __dp4a((int)w2v, (int)wB2, __dp4a((int)w1v, (int)wB1, __dp4a((int)w0v, (int)wB0, 0)));
            int o10 = __dp4a((int)w3v, (int)wA2, __dp4a((int)w2v, (int)wA1, __dp4a((int)w1v, (int)wA0, 0)));
            int o11 = __dp4a((int)w3v, (int)wB2, __dp4a((int)w2v, (int)wB1, __dp4a((int)w1v, (int)wB0, 0)));
            int mx = max(max(o00, o01), max(o10, o11));
            obp[2*t + 1] = (mx >= thc) ? (int8_t)1 : (int8_t)-1;
        }
        c0 = n0; c1 = n1; c2 = n2; c3 = n3;
    }
    __syncthreads();

    uint4* dst = (uint4*)(g_act + (size_t)img * F1);  // F1 = 392 * 16 -> uint4 clean
    const uint4* src = (const uint4*)ob;
    if (tid < 392) dst[tid] = src[tid];
}

// =============================== kernel 2: int8 mma.sync GEMM + fused epilogue ===============================
// Byte-identical to the measured-best round-9 mainloop (204.6 us): CTA tile 128x128,
// 256 threads, 8 warps 2(M)x4(N) 64x32 tiles, 2 CTAs/SM, 3-stage cp.async, KC=128,
// register-double-buffered ldsm fragments. s8 IMMA at ~940 MAC/cyc/SM is this chip's
// legacy-path ceiling (fp8 flavor: 2.5x slower, emulated) — mainloop is at its floor.

#define KC      128
#define NSTG    3
#define RSTR    144                   // padded smem row stride (bank-conflict-free)
#define STG_A   (128 * RSTR)          // 18432
#define STG_B   (128 * RSTR)          // 18432
#define STG_SZ  (STG_A + STG_B)       // 36864
#define GEMM_DSMEM (NSTG * STG_SZ)    // 110592

__device__ __forceinline__ void load_stage(const int8_t* A0, const int8_t* B0,
                                           uint32_t stg, int k0, int tid) {
    #pragma unroll
    for (int j = 0; j < 8; ++j) {                 // 2048 x 16B chunks / 256 threads
        int chn = tid + j * 256;
        if (chn < 1024) {                         // A: 128 rows x 8 granules
            int row = chn >> 3, c16 = chn & 7;
            cp16(stg + (uint32_t)row * RSTR + (uint32_t)c16 * 16,
                 A0 + (size_t)row * F1 + k0 + c16 * 16);
        } else {                                  // B: 128 rows x 8 granules
            int bc = chn - 1024;
            int row = bc >> 3, c16 = bc & 7;
            cp16(stg + STG_A + (uint32_t)row * RSTR + (uint32_t)c16 * 16,
                 B0 + (size_t)row * F1 + k0 + c16 * 16);
        }
    }
}

__global__ void __launch_bounds__(256, 2) k_gemm(
    const float* __restrict__ b2, const float* __restrict__ g2,
    const float* __restrict__ be2, const float* __restrict__ m2,
    const float* __restrict__ v2, const float* __restrict__ W3)
{
    extern __shared__ char dsm[];
    const uint32_t sb = smem_u32(dsm);
    const int tid = threadIdx.x, lane = tid & 31, wid = tid >> 5;
    const int wm = wid >> 2, wn = wid & 3;        // 2(M) x 4(N) warp grid, 64x32 tiles
    const int nt = blockIdx.x, mt = blockIdx.y;
    const int m0 = mt * 128, n0 = nt * 128;

    const int8_t* A0 = g_act + (size_t)m0 * F1;
    const int8_t* B0 = g_w2b + (size_t)n0 * F1;

    // prologue: stages 0,1
    load_stage(A0, B0, sb + 0 * STG_SZ, 0,  tid);
    asm volatile("cp.async.commit_group;" ::: "memory");
    load_stage(A0, B0, sb + 1 * STG_SZ, KC, tid);
    asm volatile("cp.async.commit_group;" ::: "memory");

    int acc[4][4][4];                             // [mb 16-rows][nb 8-cols][frag]
    #pragma unroll
    for (int i = 0; i < 4; ++i)
        #pragma unroll
        for (int j = 0; j < 4; ++j)
            #pragma unroll
            for (int r = 0; r < 4; ++r) acc[i][j][r] = 0;

    const uint32_t aoffT = (uint32_t)(wm * 64 + (lane & 7) + ((lane >> 3) & 1) * 8) * RSTR
                         + ((lane >> 4) & 1) * 16;
    const uint32_t boffT = STG_A
                         + (uint32_t)(wn * 32 + (lane & 7) + ((lane >> 4) & 1) * 8) * RSTR
                         + ((lane >> 3) & 1) * 16;

    for (int k = 0; k < 49; ++k) {
        const int buf = k - (k / 3) * 3;
        asm volatile("cp.async.wait_group 1;" ::: "memory");
        __syncthreads();
        const int kn = k + 2;
        if (kn < 49) {
            const int bn = kn - (kn / 3) * 3;
            load_stage(A0, B0, sb + bn * STG_SZ, kn * KC, tid);
        }
        asm volatile("cp.async.commit_group;" ::: "memory");

        const uint32_t sA = sb + buf * STG_SZ;
        uint32_t a[2][4][4], b[2][2][4];
        #pragma unroll
        for (int mb = 0; mb < 4; ++mb)
            ldsm4(a[0][mb], sA + aoffT + mb * (16 * RSTR));
        #pragma unroll
        for (int nbp = 0; nbp < 2; ++nbp)
            ldsm4(b[0][nbp], sA + boffT + nbp * (16 * RSTR));

        #pragma unroll
        for (int ks = 0; ks < 4; ++ks) {
            const int cur = ks & 1, nxt = cur ^ 1;
            if (ks < 3) {
                #pragma unroll
                for (int mb = 0; mb < 4; ++mb)
                    ldsm4(a[nxt][mb], sA + aoffT + mb * (16 * RSTR) + (ks + 1) * 32);
                #pragma unroll
                for (int nbp = 0; nbp < 2; ++nbp)
                    ldsm4(b[nxt][nbp], sA + boffT + nbp * (16 * RSTR) + (ks + 1) * 32);
            }
            #pragma unroll
            for (int nbp = 0; nbp < 2; ++nbp)
                #pragma unroll
                for (int mb = 0; mb < 4; ++mb) {
                    mma_s8(acc[mb][2 * nbp],     a[cur][mb], b[cur][nbp]);
                    mma_s8(acc[mb][2 * nbp + 1], a[cur][mb], b[cur][nbp] + 2);
                }
        }
    }
    __syncthreads();                                  // compute done; reuse smem

    // ---- epilogue: b2 + BN2 + hardtanh, then partial logits vs W3 ----
    float* sp = (float*)dsm;                          // [4 warp_n][128 rows][10] = 20 KB
    float* tb = (float*)(dsm + 20480);                // tables: 5*128 + 128*10 floats
    if (tid < 128) {
        int n = n0 + tid;
        tb[tid]       = b2[n];
        tb[128 + tid] = g2[n];
        tb[256 + tid] = m2[n];
        tb[384 + tid] = 1.0f / sqrtf(v2[n] + EPSV);
        tb[512 + tid] = be2[n];
    }
    for (int i = tid; i < 1280; i += 256) {
        int col = i / 10, c = i - col * 10;
        tb[640 + i] = W3[(size_t)c * HID + n0 + col];
    }
    __syncthreads();

    #pragma unroll
    for (int mb = 0; mb < 4; ++mb) {
        #pragma unroll
        for (int half = 0; half < 2; ++half) {
            int row = wm * 64 + mb * 16 + (lane >> 2) + 8 * half;
            float l10[NCLS];
            #pragma unroll
            for (int c = 0; c < NCLS; ++c) l10[c] = 0.f;
            #pragma unroll
            for (int nb = 0; nb < 4; ++nb) {
                #pragma unroll
                for (int e = 0; e < 2; ++e) {
                    int col = wn * 32 + nb * 8 + 2 * (lane & 3) + e;
                    float z = (float)acc[mb][nb][half * 2 + e] + tb[col];   // + b2 (exact int)
                    float t = tb[128 + col] * (z - tb[256 + col]);          // g2*(z-m2)
                    t *= tb[384 + col]; t += tb[512 + col];                 // *rs + be2
                    t = fminf(1.f, fmaxf(-1.f, t));                         // hardtanh
                    const float* w3c = tb + 640 + col * 10;
                    #pragma unroll
                    for (int c = 0; c < NCLS; ++c) l10[c] = fmaf(t, w3c[c], l10[c]);
                }
            }
            #pragma unroll
            for (int c = 0; c < NCLS; ++c) {
                l10[c] += __shfl_xor_sync(0xffffffffu, l10[c], 1);
                l10[c] += __shfl_xor_sync(0xffffffffu, l10[c], 2);
            }
            if ((lane & 3) == 0) {
                float* d = sp + ((size_t)wn * 128 + row) * NCLS;
                #pragma unroll
                for (int c = 0; c < NCLS; ++c) d[c] = l10[c];
            }
        }
    }
    __syncthreads();

    for (int i = tid; i < 128 * NCLS; i += 256) {
        int row = i / NCLS, c = i - row * NCLS;
        float s = sp[(0 * 128 + row) * NCLS + c] + sp[(1 * 128 + row) * NCLS + c]
                + sp[(2 * 128 + row) * NCLS + c] + sp[(3 * 128 + row) * NCLS + c];
        g_part[((size_t)nt * B_SZ + m0 + row) * NCLS + c] = s;
    }
}

// =============================== kernel 3: reduce + b3 + log_softmax ===============================
// float2-vectorized partial reads (row stride 40B, 8B-aligned); summation order identical.

__global__ void __launch_bounds__(256) k_final(const float* __restrict__ b3,
                                               float* __restrict__ out) {
    int row = blockIdx.x * 256 + threadIdx.x;     // 4096 rows
    float l[NCLS];
    #pragma unroll
    for (int c = 0; c < NCLS; ++c) l[c] = b3[c];
    #pragma unroll
    for (int p = 0; p < 16; ++p) {
        const float2* s = (const float2*)(g_part + ((size_t)p * B_SZ + row) * NCLS);
        float2 a0 = s[0], a1 = s[1], a2 = s[2], a3 = s[3], a4 = s[4];
        l[0] += a0.x; l[1] += a0.y; l[2] += a1.x; l[3] += a1.y; l[4] += a2.x;
        l[5] += a2.y; l[6] += a3.x; l[7] += a3.y; l[8] += a4.x; l[9] += a4.y;
    }
    float m = l[0];
    #pragma unroll
    for (int c = 1; c < NCLS; ++c) m = fmaxf(m, l[c]);
    float sum = 0.f;
    #pragma unroll
    for (int c = 0; c < NCLS; ++c) sum += expf(l[c] - m);
    float lse = m + logf(sum);
    #pragma unroll
    for (int c = 0; c < NCLS; ++c) out[row * NCLS + c] = l[c] - lse;
}

// =============================== launcher ===============================

extern "C" void kernel_launch(void* const* d_in, const int* in_sizes, int n_in,
                              void* d_out, int out_size) {
    const float* x   = (const float*)d_in[0];
    const float* W1  = (const float*)d_in[1];
    const float* b1  = (const float*)d_in[2];
    const float* g1  = (const float*)d_in[3];
    const float* be1 = (const float*)d_in[4];
    const float* m1  = (const float*)d_in[5];
    const float* v1  = (const float*)d_in[6];
    const float* W2  = (const float*)d_in[7];
    const float* b2  = (const float*)d_in[8];
    const float* g2  = (const float*)d_in[9];
    const float* be2 = (const float*)d_in[10];
    const float* m2  = (const float*)d_in[11];
    const float* v2  = (const float*)d_in[12];
    const float* W3  = (const float*)d_in[13];
    const float* b3  = (const float*)d_in[14];

    cudaFuncSetAttribute(k_gemm, cudaFuncAttributeMaxDynamicSharedMemorySize, GEMM_DSMEM);

    k_pre<<<B_SZ + W2B_BLKS, 448>>>(x, W1, b1, g1, be1, m1, v1, W2);
    k_gemm<<<dim3(16, 32), 256, GEMM_DSMEM>>>(b2, g2, be2, m2, v2, W3);
    k_final<<<16, 256>>>(b3, (float*)d_out);
}